// round 4
// baseline (speedup 1.0000x reference)
#include <cuda_runtime.h>
#include <cstdint>

// dilate_tensor: input (16,128,128,128) f32 NHWC -> output (16,256,256,128)
// out[n, 2*ih+1, 2*iw+1, c] = in[n, ih, iw, c]; everything else zero.
//
// C=128 floats contiguous & untouched -> each output pixel is a 512B run:
// straight copy (oh odd && ow odd) or zeros.
//
// ILP-4 layout: each 256-thread block covers 1024 consecutive float4
// (= 32 consecutive pixels, all in ONE output row -> oh, n block-uniform).
//   - even oh: pure zero block, 4 stores/thread, no index math, no loads.
//   - odd oh : per (warp, iter) one pixel; parity is warp-uniform.
// All dims powers of two -> shift/mask only.

#define C4_SHIFT   5            // 32 float4 per pixel
#define OW_MASK    255u
#define OH_MASK    255u
#define F4_PER_BLK 1024u        // 256 threads * 4
#define TOTAL_OUT_F4 (16u * 256u * 256u * 32u)   // 2^25

__global__ __launch_bounds__(256) void dilate_kernel(const float4* __restrict__ in,
                                                     float4* __restrict__ out)
{
    const uint32_t t        = threadIdx.x;
    const uint32_t base     = blockIdx.x * F4_PER_BLK;   // first f4 of block
    const uint32_t pix_base = base >> C4_SHIFT;          // 32 pixels per block
    const uint32_t oh       = (pix_base >> 8) & OH_MASK; // block-uniform
    const float4 z = make_float4(0.f, 0.f, 0.f, 0.f);

    if ((oh & 1u) == 0u) {
        // Entire block is zeros: 4 independent streaming stores per thread.
        #pragma unroll
        for (uint32_t i = 0; i < 4; i++)
            __stcs(&out[base + i * 256u + t], z);
        return;
    }

    // Odd output row: input row base (block-uniform).
    const uint32_t n    = pix_base >> 16;
    const uint32_t irow = (n << 19) | ((oh >> 1) << 12);   // input f4 row base

    // Gather phase first (maximize loads in flight), then store phase.
    float4 v[4];
    #pragma unroll
    for (uint32_t i = 0; i < 4; i++) {
        const uint32_t idx = base + i * 256u + t;
        const uint32_t ow  = (idx >> C4_SHIFT) & OW_MASK;  // warp-uniform parity
        v[i] = z;
        if (ow & 1u) {
            const uint32_t c4   = idx & 31u;
            const uint32_t iidx = irow | ((ow >> 1) << C4_SHIFT) | c4;
            v[i] = __ldcs(&in[iidx]);
        }
    }
    #pragma unroll
    for (uint32_t i = 0; i < 4; i++)
        __stcs(&out[base + i * 256u + t], v[i]);
}

extern "C" void kernel_launch(void* const* d_in, const int* in_sizes, int n_in,
                              void* d_out, int out_size)
{
    (void)in_sizes; (void)n_in; (void)out_size;
    const float4* in  = (const float4*)d_in[0];
    float4*       out = (float4*)d_out;

    const int threads = 256;
    const int blocks  = TOTAL_OUT_F4 / F4_PER_BLK;   // 32768, exact
    dilate_kernel<<<blocks, threads>>>(in, out);
}